// round 9
// baseline (speedup 1.0000x reference)
#include <cuda_runtime.h>
#include <math.h>
#include <stdint.h>

#define Bsz 64
#define Tsz 32
#define Vsz 10000
#define Vpad 10016
#define Esz 256
#define Hsz 512
#define BH (Bsz*Hsz)
#define KSPLIT 8
#define VT 157     // ceil(10000/64) v-tiles
#define LSPLIT 4   // logits split-K

// Scratch (static device globals: allocation-free)
__device__ float g_x[Bsz*Esz];
__device__ float g_h[BH];
__device__ float g_c[BH];
__device__ float g_pre[KSPLIT*4*BH];
__device__ float g_part[LSPLIT][Bsz*Vpad];

// ---------------- cp.async helpers ----------------
__device__ __forceinline__ void cp16(void* dst, const void* src) {
  uint32_t d = (uint32_t)__cvta_generic_to_shared(dst);
  asm volatile("cp.async.ca.shared.global [%0], [%1], 16;" :: "r"(d), "l"(src));
}
__device__ __forceinline__ void cp16z(void* dst, const void* src, int bytes) {
  uint32_t d = (uint32_t)__cvta_generic_to_shared(dst);
  asm volatile("cp.async.ca.shared.global [%0], [%1], 16, %2;" :: "r"(d), "l"(src), "r"(bytes));
}
#define CP_COMMIT asm volatile("cp.async.commit_group;")
#define CP_WAIT0  asm volatile("cp.async.wait_group 0;")

// ---------------- threefry2x32 (matches JAX threefry2x32_p) ----------------
__device__ __forceinline__ void tf2x32(uint32_t k0, uint32_t k1,
                                       uint32_t x0, uint32_t x1,
                                       uint32_t& o0, uint32_t& o1) {
  uint32_t ks2 = k0 ^ k1 ^ 0x1BD11BDAu;
  x0 += k0; x1 += k1;
#define TFR(R) x0 += x1; x1 = (x1 << (R)) | (x1 >> (32 - (R))); x1 ^= x0;
  TFR(13) TFR(15) TFR(26) TFR(6)
  x0 += k1; x1 += ks2 + 1u;
  TFR(17) TFR(29) TFR(16) TFR(24)
  x0 += ks2; x1 += k0 + 2u;
  TFR(13) TFR(15) TFR(26) TFR(6)
  x0 += k0; x1 += k1 + 3u;
  TFR(17) TFR(29) TFR(16) TFR(24)
  x0 += k1; x1 += ks2 + 4u;
  TFR(13) TFR(15) TFR(26) TFR(6)
  x0 += ks2; x1 += k0 + 5u;
#undef TFR
  o0 = x0; o1 = x1;
}

__device__ __forceinline__ int decode_i(uint32_t w) {
  return (w >= 0x10000u) ? (int)__uint_as_float(w) : (int)w;
}

// ---------------- init: h=c=0, x0 = emb[start_token] ----------------
__global__ void init_kernel(const uint32_t* __restrict__ start_token,
                            const float* __restrict__ emb) {
  int b = blockIdx.x, tid = threadIdx.x;
  for (int j = tid; j < Hsz; j += 256) {
    g_h[b*Hsz + j] = 0.f;
    g_c[b*Hsz + j] = 0.f;
  }
  int tok = decode_i(start_token[b]);
  if (tok < 0) tok = 0; if (tok >= Vsz) tok = Vsz - 1;
  g_x[b*Esz + tid] = emb[(size_t)tok*Esz + tid];
}

// ---------------- gates GEMM (split-K): part[ks][g] = Xk@Wk + Hk@Uk ----------------
__global__ __launch_bounds__(256) void gates_kernel(
    const float* __restrict__ Wi, const float* __restrict__ Wf,
    const float* __restrict__ Wog, const float* __restrict__ Wc,
    const float* __restrict__ Ui, const float* __restrict__ Uf,
    const float* __restrict__ Uog, const float* __restrict__ Uc)
{
  __shared__ __align__(16) float sm[12288];
  float* As = sm;
  float* Bs = sm + 6144;
  int tid = threadIdx.x;
  int nt = blockIdx.x, g = blockIdx.y, ks = blockIdx.z;
  const float* W; const float* U;
  if      (g == 0) { W = Wi;  U = Ui;  }
  else if (g == 1) { W = Wf;  U = Uf;  }
  else if (g == 2) { W = Wog; U = Uog; }
  else             { W = Wc;  U = Uc;  }
  int kbase = ks*96;
  int n0 = nt*64;

#pragma unroll
  for (int i = 0; i < 6; i++) {
    int li = tid + i*256;
    int m = li / 24, seg = li % 24;
    int kg = kbase + seg*4;
    const float* src = (kg < Esz) ? (g_x + m*Esz + kg) : (g_h + m*Hsz + (kg - Esz));
    cp16(As + m*96 + seg*4, src);
  }
#pragma unroll
  for (int i = 0; i < 6; i++) {
    int li = tid + i*256;
    int k = li >> 4, seg = li & 15;
    int kg = kbase + k;
    const float* src = (kg < Esz) ? (W + (size_t)kg*Hsz + n0 + seg*4)
                                  : (U + (size_t)(kg - Esz)*Hsz + n0 + seg*4);
    cp16(Bs + k*64 + seg*4, src);
  }
  CP_COMMIT; CP_WAIT0; __syncthreads();

  int tx = tid & 15, ty = tid >> 4;
  float acc[4][4] = {};
#pragma unroll 8
  for (int k = 0; k < 96; k++) {
    float4 b4 = *(const float4*)(Bs + k*64 + tx*4);
#pragma unroll
    for (int i = 0; i < 4; i++) {
      float a = As[(ty*4 + i)*96 + k];
      acc[i][0] = fmaf(a, b4.x, acc[i][0]);
      acc[i][1] = fmaf(a, b4.y, acc[i][1]);
      acc[i][2] = fmaf(a, b4.z, acc[i][2]);
      acc[i][3] = fmaf(a, b4.w, acc[i][3]);
    }
  }
  float* outp = g_pre + (size_t)(ks*4 + g)*BH;
#pragma unroll
  for (int i = 0; i < 4; i++) {
    int m = ty*4 + i;
    *(float4*)(outp + m*Hsz + n0 + tx*4) =
        make_float4(acc[i][0], acc[i][1], acc[i][2], acc[i][3]);
  }
}

// ---------------- cell: sum split-K parts + bias, LSTM pointwise ----------------
__global__ void cell_kernel(const float* __restrict__ bi, const float* __restrict__ bf_,
                            const float* __restrict__ bog, const float* __restrict__ bc) {
  int idx = blockIdx.x*256 + threadIdx.x;
  int h = idx & (Hsz - 1);
  float s0 = bi[h], s1 = bf_[h], s2 = bog[h], s3 = bc[h];
#pragma unroll
  for (int ks = 0; ks < KSPLIT; ks++) {
    s0 += g_pre[(size_t)(ks*4 + 0)*BH + idx];
    s1 += g_pre[(size_t)(ks*4 + 1)*BH + idx];
    s2 += g_pre[(size_t)(ks*4 + 2)*BH + idx];
    s3 += g_pre[(size_t)(ks*4 + 3)*BH + idx];
  }
  float ig = 1.f/(1.f + expf(-s0));
  float fg = 1.f/(1.f + expf(-s1));
  float og = 1.f/(1.f + expf(-s2));
  float cb = tanhf(s3);
  float c  = fg*g_c[idx] + ig*cb;
  g_c[idx] = c;
  g_h[idx] = og*tanhf(c);
}

// ---------------- logits GEMM split-K partial: part[ks] = h[:,ks*128:+128] @ Wo ----------------
// grid (157, 4), block 256. Tile 64m x 64v, K=128 in 4 chunks of 32.
__global__ __launch_bounds__(256) void logits_partial_kernel(
    const float* __restrict__ Wo)
{
  __shared__ __align__(16) float As[2][64*36];
  __shared__ __align__(16) float Bs[2][32*68];
  int tid = threadIdx.x;
  int n0 = blockIdx.x * 64;
  int kb = blockIdx.y * 128;

#pragma unroll
  for (int i = 0; i < 2; i++) {
    int li = tid + i*256; int m = li >> 3, seg = li & 7;
    cp16(&As[0][m*36 + seg*4], g_h + m*Hsz + kb + seg*4);
  }
#pragma unroll
  for (int i = 0; i < 2; i++) {
    int li = tid + i*256; int k = li >> 4, seg = li & 15;
    int col = n0 + seg*4;
    int valid = (Vsz - col)*4; if (valid > 16) valid = 16; if (valid < 0) valid = 0;
    cp16z(&Bs[0][k*68 + seg*4], Wo + (size_t)(kb + k)*Vsz + (col < Vsz ? col : 0), valid);
  }
  CP_COMMIT;

  int tx = tid & 15, ty = tid >> 4;
  float acc[4][4] = {};
  for (int c = 0; c < 4; c++) {
    CP_WAIT0; __syncthreads();
    if (c < 3) {
      int kc = kb + (c + 1)*32;
      int nb = (c + 1) & 1;
#pragma unroll
      for (int i = 0; i < 2; i++) {
        int li = tid + i*256; int m = li >> 3, seg = li & 7;
        cp16(&As[nb][m*36 + seg*4], g_h + m*Hsz + kc + seg*4);
      }
#pragma unroll
      for (int i = 0; i < 2; i++) {
        int li = tid + i*256; int k = li >> 4, seg = li & 15;
        int col = n0 + seg*4;
        int valid = (Vsz - col)*4; if (valid > 16) valid = 16; if (valid < 0) valid = 0;
        cp16z(&Bs[nb][k*68 + seg*4], Wo + (size_t)(kc + k)*Vsz + (col < Vsz ? col : 0), valid);
      }
      CP_COMMIT;
    }
    const float* Ab = As[c & 1];
    const float* Bb = Bs[c & 1];
#pragma unroll
    for (int k = 0; k < 32; k++) {
      float4 b4 = *(const float4*)(Bb + k*68 + tx*4);
#pragma unroll
      for (int i = 0; i < 4; i++) {
        float a = Ab[(ty*4 + i)*36 + k];
        acc[i][0] = fmaf(a, b4.x, acc[i][0]);
        acc[i][1] = fmaf(a, b4.y, acc[i][1]);
        acc[i][2] = fmaf(a, b4.z, acc[i][2]);
        acc[i][3] = fmaf(a, b4.w, acc[i][3]);
      }
    }
  }

  float* dst = g_part[blockIdx.y];
  int v0 = n0 + tx*4;
#pragma unroll
  for (int i = 0; i < 4; i++) {
    int m = ty*4 + i;
    if (v0 + 3 < Vsz) {
      *(float4*)(dst + (size_t)m*Vpad + v0) =
          make_float4(acc[i][0], acc[i][1], acc[i][2], acc[i][3]);
    } else {
#pragma unroll
      for (int j = 0; j < 4; j++)
        if (v0 + j < Vsz) dst[(size_t)m*Vpad + v0 + j] = acc[i][j];
    }
  }
}

// ---------------- finalize: sum partials + bo + gumbel, argmax over full row,
// teacher-force, write out (float32), embed next x. grid Bsz, block 256.
__global__ __launch_bounds__(256) void finalize_kernel(
    const uint32_t* __restrict__ input_x,
    const uint32_t* __restrict__ gn_dev, int gn_elems,
    const float* __restrict__ bo,
    const float* __restrict__ emb,
    float* __restrict__ out, int t)
{
  __shared__ float sv[256];
  __shared__ int   si[256];
  __shared__ int   stok;
  int b = blockIdx.x, tid = threadIdx.x;

  uint32_t k0, k1;
  tf2x32(0u, 42u, 0u, (uint32_t)t, k0, k1);
  const float tiny = 1.17549435e-38f;

  float bestv = -INFINITY; int besti = 0x7fffffff;
  for (int v = tid; v < Vsz; v += 256) {
    size_t off = (size_t)b*Vpad + v;
    float logit = ((g_part[0][off] + g_part[1][off]) +
                   (g_part[2][off] + g_part[3][off])) + bo[v];
    uint32_t o0, o1;
    tf2x32(k0, k1, 0u, (uint32_t)(b*Vsz + v), o0, o1);
    uint32_t bits = o0 ^ o1;
    float f = __uint_as_float((bits >> 9) | 0x3f800000u) - 1.0f;
    float u = fmaxf(tiny, f + tiny);
    float val = (-logf(-logf(u))) + logit;
    if (val > bestv) { bestv = val; besti = v; }   // ascending v: first max kept
  }
  sv[tid] = bestv; si[tid] = besti;
  __syncthreads();
  for (int s = 128; s > 0; s >>= 1) {
    if (tid < s) {
      float v2 = sv[tid + s]; int i2 = si[tid + s];
      if (v2 > sv[tid] || (v2 == sv[tid] && i2 < si[tid])) { sv[tid] = v2; si[tid] = i2; }
    }
    __syncthreads();
  }
  if (tid == 0) {
    int gn = 16;
    if (gn_dev) {
      uint32_t w0 = gn_dev[0];
      if (w0 >= 0x3F800000u && w0 < 0x4F000000u) gn = (int)__uint_as_float(w0);
      else if (w0 < 0x10000u) {
        gn = (int)w0;
        if (gn == 0 && gn_elems >= 2) {
          uint32_t w1 = gn_dev[1];
          if (w1 >= 0x3FF00000u && w1 < 0x43000000u)
            gn = (int)__hiloint2double((int)w1, (int)w0);
        }
      }
    }
    if (gn < 0) gn = 0; if (gn > Tsz) gn = Tsz;

    int tok = (t < gn) ? decode_i(input_x[b*Tsz + t]) : si[0];
    if (tok < 0) tok = 0; if (tok >= Vsz) tok = Vsz - 1;
    out[b*Tsz + t] = (float)tok;      // harness reads d_out as float32 (validated)
    stok = tok;
  }
  __syncthreads();
  g_x[b*Esz + tid] = emb[(size_t)stok*Esz + tid];
}

// ---------------- host-side input layout detection (validated round 6) ----------------
#define N_LOGICAL 18
static const long long kLogicalSz[N_LOGICAL] = {
  2048, 1, 64, 2560000,
  131072, 262144, 512,
  131072, 262144, 512,
  131072, 262144, 512,
  131072, 262144, 512,
  5120000, 10000
};
static const int ordA[18] = {0,1,2,3,4,5,6,7,8,9,10,11,12,13,14,15,16,17};
static const int ordB[17] = {0,2,3,4,5,6,7,8,9,10,11,12,13,14,15,16,17};
static const int ordC[18] = {14,8,5,11, 13,7,4,16,10, 15,9,6,17,12, 3,1,0,2};
static const int ordD[17] = {14,8,5,11, 13,7,4,16,10, 15,9,6,17,12, 3,0,2};

static bool match_order(const int* ord, int n, const int* in_sizes, int n_in, int scale) {
  if (n != n_in) return false;
  for (int p = 0; p < n; p++) {
    long long L = kLogicalSz[ord[p]];
    long long s = in_sizes[p];
    if (L == 1) { if (s != 1 && s != 4 && s != 8) return false; }
    else if (s != L * scale) return false;
  }
  return true;
}

extern "C" void kernel_launch(void* const* d_in, const int* in_sizes, int n_in,
                              void* d_out, int out_size) {
  const void* slot[N_LOGICAL];
  for (int i = 0; i < N_LOGICAL; i++) slot[i] = nullptr;
  int gn_elems = 1;

  const int* ord = nullptr; int n = 0;
  for (int sc = 1; sc <= 4 && !ord; sc *= 4) {
    if      (match_order(ordA, 18, in_sizes, n_in, sc)) { ord = ordA; n = 18; }
    else if (match_order(ordB, 17, in_sizes, n_in, sc)) { ord = ordB; n = 17; }
    else if (match_order(ordC, 18, in_sizes, n_in, sc)) { ord = ordC; n = 18; }
    else if (match_order(ordD, 17, in_sizes, n_in, sc)) { ord = ordD; n = 17; }
  }
  if (ord) {
    for (int p = 0; p < n; p++) {
      slot[ord[p]] = d_in[p];
      if (ord[p] == 1) gn_elems = (in_sizes[p] >= 8) ? 2 : 1;
    }
  } else {
    long long scale = 1;
    for (int p = 0; p < n_in; p++) if (in_sizes[p] == 10240000) scale = 4;
    int wq[4] = {4,7,10,13}, uq[4] = {5,8,11,14}, bq[4] = {6,9,12,15};
    int wi_ = 0, ui_ = 0, bi_ = 0;
    for (int p = 0; p < n_in; p++) {
      long long s = in_sizes[p];
      if      (s == 2048*scale)    slot[0]  = d_in[p];
      else if (s == 1 || s == 4 || s == 8) { slot[1] = d_in[p]; gn_elems = (s >= 8) ? 2 : 1; }
      else if (s == 64*scale)      slot[2]  = d_in[p];
      else if (s == 2560000*scale) slot[3]  = d_in[p];
      else if (s == 5120000*scale) slot[16] = d_in[p];
      else if (s == 10000*scale)   slot[17] = d_in[p];
      else if (s == 131072*scale && wi_ < 4) slot[wq[wi_++]] = d_in[p];
      else if (s == 262144*scale && ui_ < 4) slot[uq[ui_++]] = d_in[p];
      else if (s == 512*scale    && bi_ < 4) slot[bq[bi_++]] = d_in[p];
    }
  }
  for (int i = 0; i < N_LOGICAL; i++)
    if (i != 1 && slot[i] == nullptr) return;

  const uint32_t* input_x     = (const uint32_t*)slot[0];
  const uint32_t* gn_dev      = (const uint32_t*)slot[1];
  const uint32_t* start_token = (const uint32_t*)slot[2];
  const float* emb = (const float*)slot[3];
  const float* Wi  = (const float*)slot[4];
  const float* Ui  = (const float*)slot[5];
  const float* bi  = (const float*)slot[6];
  const float* Wf  = (const float*)slot[7];
  const float* Uf  = (const float*)slot[8];
  const float* bf_ = (const float*)slot[9];
  const float* Wog = (const float*)slot[10];
  const float* Uog = (const float*)slot[11];
  const float* bog = (const float*)slot[12];
  const float* Wc  = (const float*)slot[13];
  const float* Uc  = (const float*)slot[14];
  const float* bc  = (const float*)slot[15];
  const float* Wo  = (const float*)slot[16];
  const float* bo  = (const float*)slot[17];

  init_kernel<<<Bsz, 256>>>(start_token, emb);
  for (int t = 0; t < Tsz; t++) {
    gates_kernel<<<dim3(8,4,8), 256>>>(Wi, Wf, Wog, Wc, Ui, Uf, Uog, Uc);
    cell_kernel<<<BH/256, 256>>>(bi, bf_, bog, bc);
    logits_partial_kernel<<<dim3(VT,LSPLIT), 256>>>(Wo);
    finalize_kernel<<<Bsz, 256>>>(input_x, gn_dev, gn_elems, bo, emb, (float*)d_out, t);
  }
}

// round 10
// speedup vs baseline: 1.1447x; 1.1447x over previous
#include <cuda_runtime.h>
#include <math.h>
#include <stdint.h>

#define Bsz 64
#define Tsz 32
#define Vsz 10000
#define Vpad 10016
#define Esz 256
#define Hsz 512
#define BH (Bsz*Hsz)
#define KSPLIT 8
#define VT 157     // ceil(10000/64) v-tiles
#define LSPLIT 4   // logits split-K

// Scratch (static device globals: allocation-free)
__device__ float g_x[Bsz*Esz];
__device__ float g_h[BH];
__device__ float g_c[BH];
__device__ float g_pre[KSPLIT*4*BH];
__device__ float g_part[LSPLIT][Bsz*Vpad];
__device__ float g_pv[Bsz*VT];
__device__ int   g_pi[Bsz*VT];

// ---------------- cp.async helpers ----------------
__device__ __forceinline__ void cp16(void* dst, const void* src) {
  uint32_t d = (uint32_t)__cvta_generic_to_shared(dst);
  asm volatile("cp.async.ca.shared.global [%0], [%1], 16;" :: "r"(d), "l"(src));
}
__device__ __forceinline__ void cp16z(void* dst, const void* src, int bytes) {
  uint32_t d = (uint32_t)__cvta_generic_to_shared(dst);
  asm volatile("cp.async.ca.shared.global [%0], [%1], 16, %2;" :: "r"(d), "l"(src), "r"(bytes));
}
#define CP_COMMIT asm volatile("cp.async.commit_group;")
#define CP_WAIT0  asm volatile("cp.async.wait_group 0;")

// ---------------- threefry2x32 (matches JAX threefry2x32_p) ----------------
__device__ __forceinline__ void tf2x32(uint32_t k0, uint32_t k1,
                                       uint32_t x0, uint32_t x1,
                                       uint32_t& o0, uint32_t& o1) {
  uint32_t ks2 = k0 ^ k1 ^ 0x1BD11BDAu;
  x0 += k0; x1 += k1;
#define TFR(R) x0 += x1; x1 = (x1 << (R)) | (x1 >> (32 - (R))); x1 ^= x0;
  TFR(13) TFR(15) TFR(26) TFR(6)
  x0 += k1; x1 += ks2 + 1u;
  TFR(17) TFR(29) TFR(16) TFR(24)
  x0 += ks2; x1 += k0 + 2u;
  TFR(13) TFR(15) TFR(26) TFR(6)
  x0 += k0; x1 += k1 + 3u;
  TFR(17) TFR(29) TFR(16) TFR(24)
  x0 += k1; x1 += ks2 + 4u;
  TFR(13) TFR(15) TFR(26) TFR(6)
  x0 += ks2; x1 += k0 + 5u;
#undef TFR
  o0 = x0; o1 = x1;
}

__device__ __forceinline__ int decode_i(uint32_t w) {
  return (w >= 0x10000u) ? (int)__uint_as_float(w) : (int)w;
}

// ---------------- init: h=c=0, x0 = emb[start_token] ----------------
__global__ void init_kernel(const uint32_t* __restrict__ start_token,
                            const float* __restrict__ emb) {
  int b = blockIdx.x, tid = threadIdx.x;
  for (int j = tid; j < Hsz; j += 256) {
    g_h[b*Hsz + j] = 0.f;
    g_c[b*Hsz + j] = 0.f;
  }
  int tok = decode_i(start_token[b]);
  if (tok < 0) tok = 0; if (tok >= Vsz) tok = Vsz - 1;
  g_x[b*Esz + tid] = emb[(size_t)tok*Esz + tid];
}

// ---------------- gates GEMM (split-K): part[ks][g] = Xk@Wk + Hk@Uk ----------------
__global__ __launch_bounds__(256) void gates_kernel(
    const float* __restrict__ Wi, const float* __restrict__ Wf,
    const float* __restrict__ Wog, const float* __restrict__ Wc,
    const float* __restrict__ Ui, const float* __restrict__ Uf,
    const float* __restrict__ Uog, const float* __restrict__ Uc)
{
  __shared__ __align__(16) float sm[12288];
  float* As = sm;
  float* Bs = sm + 6144;
  int tid = threadIdx.x;
  int nt = blockIdx.x, g = blockIdx.y, ks = blockIdx.z;
  const float* W; const float* U;
  if      (g == 0) { W = Wi;  U = Ui;  }
  else if (g == 1) { W = Wf;  U = Uf;  }
  else if (g == 2) { W = Wog; U = Uog; }
  else             { W = Wc;  U = Uc;  }
  int kbase = ks*96;
  int n0 = nt*64;

#pragma unroll
  for (int i = 0; i < 6; i++) {
    int li = tid + i*256;
    int m = li / 24, seg = li % 24;
    int kg = kbase + seg*4;
    const float* src = (kg < Esz) ? (g_x + m*Esz + kg) : (g_h + m*Hsz + (kg - Esz));
    cp16(As + m*96 + seg*4, src);
  }
#pragma unroll
  for (int i = 0; i < 6; i++) {
    int li = tid + i*256;
    int k = li >> 4, seg = li & 15;
    int kg = kbase + k;
    const float* src = (kg < Esz) ? (W + (size_t)kg*Hsz + n0 + seg*4)
                                  : (U + (size_t)(kg - Esz)*Hsz + n0 + seg*4);
    cp16(Bs + k*64 + seg*4, src);
  }
  CP_COMMIT; CP_WAIT0; __syncthreads();

  int tx = tid & 15, ty = tid >> 4;
  float acc[4][4] = {};
#pragma unroll 8
  for (int k = 0; k < 96; k++) {
    float4 b4 = *(const float4*)(Bs + k*64 + tx*4);
#pragma unroll
    for (int i = 0; i < 4; i++) {
      float a = As[(ty*4 + i)*96 + k];
      acc[i][0] = fmaf(a, b4.x, acc[i][0]);
      acc[i][1] = fmaf(a, b4.y, acc[i][1]);
      acc[i][2] = fmaf(a, b4.z, acc[i][2]);
      acc[i][3] = fmaf(a, b4.w, acc[i][3]);
    }
  }
  float* outp = g_pre + (size_t)(ks*4 + g)*BH;
#pragma unroll
  for (int i = 0; i < 4; i++) {
    int m = ty*4 + i;
    *(float4*)(outp + m*Hsz + n0 + tx*4) =
        make_float4(acc[i][0], acc[i][1], acc[i][2], acc[i][3]);
  }
}

// ---------------- cell: sum split-K parts + bias, LSTM pointwise ----------------
__global__ void cell_kernel(const float* __restrict__ bi, const float* __restrict__ bf_,
                            const float* __restrict__ bog, const float* __restrict__ bc) {
  int idx = blockIdx.x*256 + threadIdx.x;
  int h = idx & (Hsz - 1);
  float s0 = bi[h], s1 = bf_[h], s2 = bog[h], s3 = bc[h];
#pragma unroll
  for (int ks = 0; ks < KSPLIT; ks++) {
    s0 += g_pre[(size_t)(ks*4 + 0)*BH + idx];
    s1 += g_pre[(size_t)(ks*4 + 1)*BH + idx];
    s2 += g_pre[(size_t)(ks*4 + 2)*BH + idx];
    s3 += g_pre[(size_t)(ks*4 + 3)*BH + idx];
  }
  float ig = 1.f/(1.f + expf(-s0));
  float fg = 1.f/(1.f + expf(-s1));
  float og = 1.f/(1.f + expf(-s2));
  float cb = tanhf(s3);
  float c  = fg*g_c[idx] + ig*cb;
  g_c[idx] = c;
  g_h[idx] = og*tanhf(c);
}

// ---------------- logits GEMM split-K partial: part[ks] = h[:,ks*128:+128] @ Wo ----------------
// grid (157, 4), block 256. Tile 64m x 64v, K=128 in 4 chunks of 32.
__global__ __launch_bounds__(256) void logits_partial_kernel(
    const float* __restrict__ Wo)
{
  __shared__ __align__(16) float As[2][64*36];
  __shared__ __align__(16) float Bs[2][32*68];
  int tid = threadIdx.x;
  int n0 = blockIdx.x * 64;
  int kb = blockIdx.y * 128;

#pragma unroll
  for (int i = 0; i < 2; i++) {
    int li = tid + i*256; int m = li >> 3, seg = li & 7;
    cp16(&As[0][m*36 + seg*4], g_h + m*Hsz + kb + seg*4);
  }
#pragma unroll
  for (int i = 0; i < 2; i++) {
    int li = tid + i*256; int k = li >> 4, seg = li & 15;
    int col = n0 + seg*4;
    int valid = (Vsz - col)*4; if (valid > 16) valid = 16; if (valid < 0) valid = 0;
    cp16z(&Bs[0][k*68 + seg*4], Wo + (size_t)(kb + k)*Vsz + (col < Vsz ? col : 0), valid);
  }
  CP_COMMIT;

  int tx = tid & 15, ty = tid >> 4;
  float acc[4][4] = {};
  for (int c = 0; c < 4; c++) {
    CP_WAIT0; __syncthreads();
    if (c < 3) {
      int kc = kb + (c + 1)*32;
      int nb = (c + 1) & 1;
#pragma unroll
      for (int i = 0; i < 2; i++) {
        int li = tid + i*256; int m = li >> 3, seg = li & 7;
        cp16(&As[nb][m*36 + seg*4], g_h + m*Hsz + kc + seg*4);
      }
#pragma unroll
      for (int i = 0; i < 2; i++) {
        int li = tid + i*256; int k = li >> 4, seg = li & 15;
        int col = n0 + seg*4;
        int valid = (Vsz - col)*4; if (valid > 16) valid = 16; if (valid < 0) valid = 0;
        cp16z(&Bs[nb][k*68 + seg*4], Wo + (size_t)(kc + k)*Vsz + (col < Vsz ? col : 0), valid);
      }
      CP_COMMIT;
    }
    const float* Ab = As[c & 1];
    const float* Bb = Bs[c & 1];
#pragma unroll
    for (int k = 0; k < 32; k++) {
      float4 b4 = *(const float4*)(Bb + k*68 + tx*4);
#pragma unroll
      for (int i = 0; i < 4; i++) {
        float a = Ab[(ty*4 + i)*36 + k];
        acc[i][0] = fmaf(a, b4.x, acc[i][0]);
        acc[i][1] = fmaf(a, b4.y, acc[i][1]);
        acc[i][2] = fmaf(a, b4.z, acc[i][2]);
        acc[i][3] = fmaf(a, b4.w, acc[i][3]);
      }
    }
  }

  float* dst = g_part[blockIdx.y];
  int v0 = n0 + tx*4;
#pragma unroll
  for (int i = 0; i < 4; i++) {
    int m = ty*4 + i;
    if (v0 + 3 < Vsz) {
      *(float4*)(dst + (size_t)m*Vpad + v0) =
          make_float4(acc[i][0], acc[i][1], acc[i][2], acc[i][3]);
    } else {
#pragma unroll
      for (int j = 0; j < 4; j++)
        if (v0 + j < Vsz) dst[(size_t)m*Vpad + v0 + j] = acc[i][j];
    }
  }
}

// ---------------- combine: sum 4 partials + bo + gumbel, per-tile argmax ----------------
// grid VT=157, block 256. Round-8 validated epilogue semantics.
__global__ __launch_bounds__(256) void combine_kernel(const float* __restrict__ bo, int t)
{
  int tid = threadIdx.x;
  int n0 = blockIdx.x * 64;
  int tx = tid & 15, ty = tid >> 4;

  uint32_t k0, k1;
  tf2x32(0u, 42u, 0u, (uint32_t)t, k0, k1);
  const float tiny = 1.17549435e-38f;

#pragma unroll
  for (int i = 0; i < 4; i++) {
    int m = ty*4 + i;
    float bestv = -INFINITY; int besti = 0x7fffffff;
#pragma unroll
    for (int j = 0; j < 4; j++) {
      int v = n0 + tx*4 + j;
      float val = -INFINITY;
      if (v < Vsz) {
        size_t off = (size_t)m*Vpad + v;
        float logit = ((g_part[0][off] + g_part[1][off]) +
                       (g_part[2][off] + g_part[3][off])) + bo[v];
        uint32_t o0, o1;
        tf2x32(k0, k1, 0u, (uint32_t)(m*Vsz + v), o0, o1);
        uint32_t bits = o0 ^ o1;
        float f = __uint_as_float((bits >> 9) | 0x3f800000u) - 1.0f;
        float u = fmaxf(tiny, f + tiny);
        val = (-logf(-logf(u))) + logit;
      }
      if (val > bestv) { bestv = val; besti = v; }
    }
#pragma unroll
    for (int s = 8; s > 0; s >>= 1) {
      float ov = __shfl_xor_sync(0xffffffffu, bestv, s, 16);
      int   oi = __shfl_xor_sync(0xffffffffu, besti, s, 16);
      if (ov > bestv || (ov == bestv && oi < besti)) { bestv = ov; besti = oi; }
    }
    if (tx == 0) {
      g_pv[m*VT + blockIdx.x] = bestv;
      g_pi[m*VT + blockIdx.x] = besti;
    }
  }
}

// ---------------- finalize: reduce tiles, teacher-force, write out, embed ----------------
__global__ void finalize_kernel(const uint32_t* __restrict__ input_x,
                                const uint32_t* __restrict__ gn_dev, int gn_elems,
                                const float* __restrict__ emb,
                                float* __restrict__ out, int t)
{
  __shared__ float sv[256];
  __shared__ int   si[256];
  __shared__ int   stok;
  int b = blockIdx.x, tid = threadIdx.x;

  float v = -INFINITY; int idx = 0x7fffffff;
  if (tid < VT) { v = g_pv[b*VT + tid]; idx = g_pi[b*VT + tid]; }
  sv[tid] = v; si[tid] = idx;
  __syncthreads();
  for (int s = 128; s > 0; s >>= 1) {
    if (tid < s) {
      float v2 = sv[tid + s]; int i2 = si[tid + s];
      if (v2 > sv[tid] || (v2 == sv[tid] && i2 < si[tid])) { sv[tid] = v2; si[tid] = i2; }
    }
    __syncthreads();
  }
  if (tid == 0) {
    int gn = 16;
    if (gn_dev) {
      uint32_t w0 = gn_dev[0];
      if (w0 >= 0x3F800000u && w0 < 0x4F000000u) gn = (int)__uint_as_float(w0);
      else if (w0 < 0x10000u) {
        gn = (int)w0;
        if (gn == 0 && gn_elems >= 2) {
          uint32_t w1 = gn_dev[1];
          if (w1 >= 0x3FF00000u && w1 < 0x43000000u)
            gn = (int)__hiloint2double((int)w1, (int)w0);
        }
      }
    }
    if (gn < 0) gn = 0; if (gn > Tsz) gn = Tsz;

    int tok = (t < gn) ? decode_i(input_x[b*Tsz + t]) : si[0];
    if (tok < 0) tok = 0; if (tok >= Vsz) tok = Vsz - 1;
    out[b*Tsz + t] = (float)tok;   // harness reads d_out as float32 (validated)
    stok = tok;
  }
  __syncthreads();
  g_x[b*Esz + tid] = emb[(size_t)stok*Esz + tid];
}

// ---------------- host-side input layout detection (validated round 6) ----------------
#define N_LOGICAL 18
static const long long kLogicalSz[N_LOGICAL] = {
  2048, 1, 64, 2560000,
  131072, 262144, 512,
  131072, 262144, 512,
  131072, 262144, 512,
  131072, 262144, 512,
  5120000, 10000
};
static const int ordA[18] = {0,1,2,3,4,5,6,7,8,9,10,11,12,13,14,15,16,17};
static const int ordB[17] = {0,2,3,4,5,6,7,8,9,10,11,12,13,14,15,16,17};
static const int ordC[18] = {14,8,5,11, 13,7,4,16,10, 15,9,6,17,12, 3,1,0,2};
static const int ordD[17] = {14,8,5,11, 13,7,4,16,10, 15,9,6,17,12, 3,0,2};

static bool match_order(const int* ord, int n, const int* in_sizes, int n_in, int scale) {
  if (n != n_in) return false;
  for (int p = 0; p < n; p++) {
    long long L = kLogicalSz[ord[p]];
    long long s = in_sizes[p];
    if (L == 1) { if (s != 1 && s != 4 && s != 8) return false; }
    else if (s != L * scale) return false;
  }
  return true;
}

extern "C" void kernel_launch(void* const* d_in, const int* in_sizes, int n_in,
                              void* d_out, int out_size) {
  const void* slot[N_LOGICAL];
  for (int i = 0; i < N_LOGICAL; i++) slot[i] = nullptr;
  int gn_elems = 1;

  const int* ord = nullptr; int n = 0;
  for (int sc = 1; sc <= 4 && !ord; sc *= 4) {
    if      (match_order(ordA, 18, in_sizes, n_in, sc)) { ord = ordA; n = 18; }
    else if (match_order(ordB, 17, in_sizes, n_in, sc)) { ord = ordB; n = 17; }
    else if (match_order(ordC, 18, in_sizes, n_in, sc)) { ord = ordC; n = 18; }
    else if (match_order(ordD, 17, in_sizes, n_in, sc)) { ord = ordD; n = 17; }
  }
  if (ord) {
    for (int p = 0; p < n; p++) {
      slot[ord[p]] = d_in[p];
      if (ord[p] == 1) gn_elems = (in_sizes[p] >= 8) ? 2 : 1;
    }
  } else {
    long long scale = 1;
    for (int p = 0; p < n_in; p++) if (in_sizes[p] == 10240000) scale = 4;
    int wq[4] = {4,7,10,13}, uq[4] = {5,8,11,14}, bq[4] = {6,9,12,15};
    int wi_ = 0, ui_ = 0, bi_ = 0;
    for (int p = 0; p < n_in; p++) {
      long long s = in_sizes[p];
      if      (s == 2048*scale)    slot[0]  = d_in[p];
      else if (s == 1 || s == 4 || s == 8) { slot[1] = d_in[p]; gn_elems = (s >= 8) ? 2 : 1; }
      else if (s == 64*scale)      slot[2]  = d_in[p];
      else if (s == 2560000*scale) slot[3]  = d_in[p];
      else if (s == 5120000*scale) slot[16] = d_in[p];
      else if (s == 10000*scale)   slot[17] = d_in[p];
      else if (s == 131072*scale && wi_ < 4) slot[wq[wi_++]] = d_in[p];
      else if (s == 262144*scale && ui_ < 4) slot[uq[ui_++]] = d_in[p];
      else if (s == 512*scale    && bi_ < 4) slot[bq[bi_++]] = d_in[p];
    }
  }
  for (int i = 0; i < N_LOGICAL; i++)
    if (i != 1 && slot[i] == nullptr) return;

  const uint32_t* input_x     = (const uint32_t*)slot[0];
  const uint32_t* gn_dev      = (const uint32_t*)slot[1];
  const uint32_t* start_token = (const uint32_t*)slot[2];
  const float* emb = (const float*)slot[3];
  const float* Wi  = (const float*)slot[4];
  const float* Ui  = (const float*)slot[5];
  const float* bi  = (const float*)slot[6];
  const float* Wf  = (const float*)slot[7];
  const float* Uf  = (const float*)slot[8];
  const float* bf_ = (const float*)slot[9];
  const float* Wog = (const float*)slot[10];
  const float* Uog = (const float*)slot[11];
  const float* bog = (const float*)slot[12];
  const float* Wc  = (const float*)slot[13];
  const float* Uc  = (const float*)slot[14];
  const float* bc  = (const float*)slot[15];
  const float* Wo  = (const float*)slot[16];
  const float* bo  = (const float*)slot[17];

  init_kernel<<<Bsz, 256>>>(start_token, emb);
  for (int t = 0; t < Tsz; t++) {
    gates_kernel<<<dim3(8,4,8), 256>>>(Wi, Wf, Wog, Wc, Ui, Uf, Uog, Uc);
    cell_kernel<<<BH/256, 256>>>(bi, bf_, bog, bc);
    logits_partial_kernel<<<dim3(VT,LSPLIT), 256>>>(Wo);
    combine_kernel<<<VT, 256>>>(bo, t);
    finalize_kernel<<<Bsz, 256>>>(input_x, gn_dev, gn_elems, emb, (float*)d_out, t);
  }
}

// round 11
// speedup vs baseline: 1.1685x; 1.0208x over previous
#include <cuda_runtime.h>
#include <math.h>
#include <stdint.h>

#define Bsz 64
#define Tsz 32
#define Vsz 10000
#define Vpad 10016
#define Esz 256
#define Hsz 512
#define BH (Bsz*Hsz)
#define KSPLIT 8
#define VT 157     // ceil(10000/64) v-tiles
#define LSPLIT 4   // logits split-K

// Scratch (static device globals: allocation-free)
__device__ float g_x[Bsz*Esz];
__device__ float g_h[BH];
__device__ float g_c[BH];
__device__ float g_pre[KSPLIT*4*BH];
__device__ float g_part[LSPLIT][Bsz*Vpad];
__device__ float g_pv[Bsz*VT];
__device__ int   g_pi[Bsz*VT];

// ---------------- cp.async helpers ----------------
__device__ __forceinline__ void cp16(void* dst, const void* src) {
  uint32_t d = (uint32_t)__cvta_generic_to_shared(dst);
  asm volatile("cp.async.ca.shared.global [%0], [%1], 16;" :: "r"(d), "l"(src));
}
__device__ __forceinline__ void cp16z(void* dst, const void* src, int bytes) {
  uint32_t d = (uint32_t)__cvta_generic_to_shared(dst);
  asm volatile("cp.async.ca.shared.global [%0], [%1], 16, %2;" :: "r"(d), "l"(src), "r"(bytes));
}
#define CP_COMMIT asm volatile("cp.async.commit_group;")
#define CP_WAIT0  asm volatile("cp.async.wait_group 0;")

// ---------------- packed f32x2 FMA (sm_103a FFMA2; per-lane .rn rounding) ----
#define FMA2(acc, a2, b2) \
  asm("fma.rn.f32x2 %0, %1, %2, %0;" : "+l"(acc) : "l"(a2), "l"(b2))
#define PACK_DUP(dst, s) \
  asm("mov.b64 %0, {%1, %1};" : "=l"(dst) : "f"(s))
#define UNPACK2(lo, hi, p) \
  asm("mov.b64 {%0, %1}, %2;" : "=f"(lo), "=f"(hi) : "l"(p))

// ---------------- threefry2x32 (matches JAX threefry2x32_p) ----------------
__device__ __forceinline__ void tf2x32(uint32_t k0, uint32_t k1,
                                       uint32_t x0, uint32_t x1,
                                       uint32_t& o0, uint32_t& o1) {
  uint32_t ks2 = k0 ^ k1 ^ 0x1BD11BDAu;
  x0 += k0; x1 += k1;
#define TFR(R) x0 += x1; x1 = (x1 << (R)) | (x1 >> (32 - (R))); x1 ^= x0;
  TFR(13) TFR(15) TFR(26) TFR(6)
  x0 += k1; x1 += ks2 + 1u;
  TFR(17) TFR(29) TFR(16) TFR(24)
  x0 += ks2; x1 += k0 + 2u;
  TFR(13) TFR(15) TFR(26) TFR(6)
  x0 += k0; x1 += k1 + 3u;
  TFR(17) TFR(29) TFR(16) TFR(24)
  x0 += k1; x1 += ks2 + 4u;
  TFR(13) TFR(15) TFR(26) TFR(6)
  x0 += ks2; x1 += k0 + 5u;
#undef TFR
  o0 = x0; o1 = x1;
}

__device__ __forceinline__ int decode_i(uint32_t w) {
  return (w >= 0x10000u) ? (int)__uint_as_float(w) : (int)w;
}

// ---------------- init: h=c=0, x0 = emb[start_token] ----------------
__global__ void init_kernel(const uint32_t* __restrict__ start_token,
                            const float* __restrict__ emb) {
  int b = blockIdx.x, tid = threadIdx.x;
  for (int j = tid; j < Hsz; j += 256) {
    g_h[b*Hsz + j] = 0.f;
    g_c[b*Hsz + j] = 0.f;
  }
  int tok = decode_i(start_token[b]);
  if (tok < 0) tok = 0; if (tok >= Vsz) tok = Vsz - 1;
  g_x[b*Esz + tid] = emb[(size_t)tok*Esz + tid];
}

// ---------------- gates GEMM (split-K): part[ks][g] = Xk@Wk + Hk@Uk ----------------
__global__ __launch_bounds__(256) void gates_kernel(
    const float* __restrict__ Wi, const float* __restrict__ Wf,
    const float* __restrict__ Wog, const float* __restrict__ Wc,
    const float* __restrict__ Ui, const float* __restrict__ Uf,
    const float* __restrict__ Uog, const float* __restrict__ Uc)
{
  __shared__ __align__(16) float sm[12288];
  float* As = sm;
  float* Bs = sm + 6144;
  int tid = threadIdx.x;
  int nt = blockIdx.x, g = blockIdx.y, ks = blockIdx.z;
  const float* W; const float* U;
  if      (g == 0) { W = Wi;  U = Ui;  }
  else if (g == 1) { W = Wf;  U = Uf;  }
  else if (g == 2) { W = Wog; U = Uog; }
  else             { W = Wc;  U = Uc;  }
  int kbase = ks*96;
  int n0 = nt*64;

#pragma unroll
  for (int i = 0; i < 6; i++) {
    int li = tid + i*256;
    int m = li / 24, seg = li % 24;
    int kg = kbase + seg*4;
    const float* src = (kg < Esz) ? (g_x + m*Esz + kg) : (g_h + m*Hsz + (kg - Esz));
    cp16(As + m*96 + seg*4, src);
  }
#pragma unroll
  for (int i = 0; i < 6; i++) {
    int li = tid + i*256;
    int k = li >> 4, seg = li & 15;
    int kg = kbase + k;
    const float* src = (kg < Esz) ? (W + (size_t)kg*Hsz + n0 + seg*4)
                                  : (U + (size_t)(kg - Esz)*Hsz + n0 + seg*4);
    cp16(Bs + k*64 + seg*4, src);
  }
  CP_COMMIT; CP_WAIT0; __syncthreads();

  int tx = tid & 15, ty = tid >> 4;
  unsigned long long acc2[4][2] = {};
#pragma unroll 8
  for (int k = 0; k < 96; k++) {
    ulonglong2 b2 = *(const ulonglong2*)(Bs + k*64 + tx*4);
#pragma unroll
    for (int i = 0; i < 4; i++) {
      float a = As[(ty*4 + i)*96 + k];
      unsigned long long aa; PACK_DUP(aa, a);
      FMA2(acc2[i][0], aa, b2.x);
      FMA2(acc2[i][1], aa, b2.y);
    }
  }
  float* outp = g_pre + (size_t)(ks*4 + g)*BH;
#pragma unroll
  for (int i = 0; i < 4; i++) {
    int m = ty*4 + i;
    float v0, v1, v2, v3;
    UNPACK2(v0, v1, acc2[i][0]);
    UNPACK2(v2, v3, acc2[i][1]);
    *(float4*)(outp + m*Hsz + n0 + tx*4) = make_float4(v0, v1, v2, v3);
  }
}

// ---------------- cell: sum split-K parts + bias, LSTM pointwise ----------------
__global__ void cell_kernel(const float* __restrict__ bi, const float* __restrict__ bf_,
                            const float* __restrict__ bog, const float* __restrict__ bc) {
  int idx = blockIdx.x*256 + threadIdx.x;
  int h = idx & (Hsz - 1);
  float s0 = bi[h], s1 = bf_[h], s2 = bog[h], s3 = bc[h];
#pragma unroll
  for (int ks = 0; ks < KSPLIT; ks++) {
    s0 += g_pre[(size_t)(ks*4 + 0)*BH + idx];
    s1 += g_pre[(size_t)(ks*4 + 1)*BH + idx];
    s2 += g_pre[(size_t)(ks*4 + 2)*BH + idx];
    s3 += g_pre[(size_t)(ks*4 + 3)*BH + idx];
  }
  float ig = 1.f/(1.f + expf(-s0));
  float fg = 1.f/(1.f + expf(-s1));
  float og = 1.f/(1.f + expf(-s2));
  float cb = tanhf(s3);
  float c  = fg*g_c[idx] + ig*cb;
  g_c[idx] = c;
  g_h[idx] = og*tanhf(c);
}

// ---------------- logits GEMM split-K partial: part[ks] = h[:,ks*128:+128] @ Wo ----------------
// grid (157, 4), block 256. Tile 64m x 64v, K=128 in 4 chunks of 32.
// Inner loop uses packed f32x2 FMA across the v dimension: per-accumulator
// k-order identical to scalar code -> bit-identical results.
__global__ __launch_bounds__(256) void logits_partial_kernel(
    const float* __restrict__ Wo)
{
  __shared__ __align__(16) float As[2][64*36];
  __shared__ __align__(16) float Bs[2][32*68];
  int tid = threadIdx.x;
  int n0 = blockIdx.x * 64;
  int kb = blockIdx.y * 128;

#pragma unroll
  for (int i = 0; i < 2; i++) {
    int li = tid + i*256; int m = li >> 3, seg = li & 7;
    cp16(&As[0][m*36 + seg*4], g_h + m*Hsz + kb + seg*4);
  }
#pragma unroll
  for (int i = 0; i < 2; i++) {
    int li = tid + i*256; int k = li >> 4, seg = li & 15;
    int col = n0 + seg*4;
    int valid = (Vsz - col)*4; if (valid > 16) valid = 16; if (valid < 0) valid = 0;
    cp16z(&Bs[0][k*68 + seg*4], Wo + (size_t)(kb + k)*Vsz + (col < Vsz ? col : 0), valid);
  }
  CP_COMMIT;

  int tx = tid & 15, ty = tid >> 4;
  unsigned long long acc2[4][2] = {};
  for (int c = 0; c < 4; c++) {
    CP_WAIT0; __syncthreads();
    if (c < 3) {
      int kc = kb + (c + 1)*32;
      int nb = (c + 1) & 1;
#pragma unroll
      for (int i = 0; i < 2; i++) {
        int li = tid + i*256; int m = li >> 3, seg = li & 7;
        cp16(&As[nb][m*36 + seg*4], g_h + m*Hsz + kc + seg*4);
      }
#pragma unroll
      for (int i = 0; i < 2; i++) {
        int li = tid + i*256; int k = li >> 4, seg = li & 15;
        int col = n0 + seg*4;
        int valid = (Vsz - col)*4; if (valid > 16) valid = 16; if (valid < 0) valid = 0;
        cp16z(&Bs[nb][k*68 + seg*4], Wo + (size_t)(kc + k)*Vsz + (col < Vsz ? col : 0), valid);
      }
      CP_COMMIT;
    }
    const float* Ab = As[c & 1];
    const float* Bb = Bs[c & 1];
#pragma unroll
    for (int k = 0; k < 32; k++) {
      ulonglong2 b2 = *(const ulonglong2*)(Bb + k*68 + tx*4);
#pragma unroll
      for (int i = 0; i < 4; i++) {
        float a = Ab[(ty*4 + i)*36 + k];
        unsigned long long aa; PACK_DUP(aa, a);
        FMA2(acc2[i][0], aa, b2.x);
        FMA2(acc2[i][1], aa, b2.y);
      }
    }
  }

  float* dst = g_part[blockIdx.y];
  int v0 = n0 + tx*4;
#pragma unroll
  for (int i = 0; i < 4; i++) {
    int m = ty*4 + i;
    float a0, a1, a2, a3;
    UNPACK2(a0, a1, acc2[i][0]);
    UNPACK2(a2, a3, acc2[i][1]);
    if (v0 + 3 < Vsz) {
      *(float4*)(dst + (size_t)m*Vpad + v0) = make_float4(a0, a1, a2, a3);
    } else {
      float av[4] = {a0, a1, a2, a3};
#pragma unroll
      for (int j = 0; j < 4; j++)
        if (v0 + j < Vsz) dst[(size_t)m*Vpad + v0 + j] = av[j];
    }
  }
}

// ---------------- combine: sum 4 partials + bo + gumbel, per-tile argmax ----------------
// grid VT=157, block 256. Round-8 validated epilogue semantics.
__global__ __launch_bounds__(256) void combine_kernel(const float* __restrict__ bo, int t)
{
  int tid = threadIdx.x;
  int n0 = blockIdx.x * 64;
  int tx = tid & 15, ty = tid >> 4;

  uint32_t k0, k1;
  tf2x32(0u, 42u, 0u, (uint32_t)t, k0, k1);
  const float tiny = 1.17549435e-38f;

#pragma unroll
  for (int i = 0; i < 4; i++) {
    int m = ty*4 + i;
    float bestv = -INFINITY; int besti = 0x7fffffff;
#pragma unroll
    for (int j = 0; j < 4; j++) {
      int v = n0 + tx*4 + j;
      float val = -INFINITY;
      if (v < Vsz) {
        size_t off = (size_t)m*Vpad + v;
        float logit = ((g_part[0][off] + g_part[1][off]) +
                       (g_part[2][off] + g_part[3][off])) + bo[v];
        uint32_t o0, o1;
        tf2x32(k0, k1, 0u, (uint32_t)(m*Vsz + v), o0, o1);
        uint32_t bits = o0 ^ o1;
        float f = __uint_as_float((bits >> 9) | 0x3f800000u) - 1.0f;
        float u = fmaxf(tiny, f + tiny);
        val = (-logf(-logf(u))) + logit;
      }
      if (val > bestv) { bestv = val; besti = v; }
    }
#pragma unroll
    for (int s = 8; s > 0; s >>= 1) {
      float ov = __shfl_xor_sync(0xffffffffu, bestv, s, 16);
      int   oi = __shfl_xor_sync(0xffffffffu, besti, s, 16);
      if (ov > bestv || (ov == bestv && oi < besti)) { bestv = ov; besti = oi; }
    }
    if (tx == 0) {
      g_pv[m*VT + blockIdx.x] = bestv;
      g_pi[m*VT + blockIdx.x] = besti;
    }
  }
}

// ---------------- finalize: reduce tiles, teacher-force, write out, embed ----------------
__global__ void finalize_kernel(const uint32_t* __restrict__ input_x,
                                const uint32_t* __restrict__ gn_dev, int gn_elems,
                                const float* __restrict__ emb,
                                float* __restrict__ out, int t)
{
  __shared__ float sv[256];
  __shared__ int   si[256];
  __shared__ int   stok;
  int b = blockIdx.x, tid = threadIdx.x;

  float v = -INFINITY; int idx = 0x7fffffff;
  if (tid < VT) { v = g_pv[b*VT + tid]; idx = g_pi[b*VT + tid]; }
  sv[tid] = v; si[tid] = idx;
  __syncthreads();
  for (int s = 128; s > 0; s >>= 1) {
    if (tid < s) {
      float v2 = sv[tid + s]; int i2 = si[tid + s];
      if (v2 > sv[tid] || (v2 == sv[tid] && i2 < si[tid])) { sv[tid] = v2; si[tid] = i2; }
    }
    __syncthreads();
  }
  if (tid == 0) {
    int gn = 16;
    if (gn_dev) {
      uint32_t w0 = gn_dev[0];
      if (w0 >= 0x3F800000u && w0 < 0x4F000000u) gn = (int)__uint_as_float(w0);
      else if (w0 < 0x10000u) {
        gn = (int)w0;
        if (gn == 0 && gn_elems >= 2) {
          uint32_t w1 = gn_dev[1];
          if (w1 >= 0x3FF00000u && w1 < 0x43000000u)
            gn = (int)__hiloint2double((int)w1, (int)w0);
        }
      }
    }
    if (gn < 0) gn = 0; if (gn > Tsz) gn = Tsz;

    int tok = (t < gn) ? decode_i(input_x[b*Tsz + t]) : si[0];
    if (tok < 0) tok = 0; if (tok >= Vsz) tok = Vsz - 1;
    out[b*Tsz + t] = (float)tok;   // harness reads d_out as float32 (validated)
    stok = tok;
  }
  __syncthreads();
  g_x[b*Esz + tid] = emb[(size_t)stok*Esz + tid];
}

// ---------------- host-side input layout detection (validated round 6) ----------------
#define N_LOGICAL 18
static const long long kLogicalSz[N_LOGICAL] = {
  2048, 1, 64, 2560000,
  131072, 262144, 512,
  131072, 262144, 512,
  131072, 262144, 512,
  131072, 262144, 512,
  5120000, 10000
};
static const int ordA[18] = {0,1,2,3,4,5,6,7,8,9,10,11,12,13,14,15,16,17};
static const int ordB[17] = {0,2,3,4,5,6,7,8,9,10,11,12,13,14,15,16,17};
static const int ordC[18] = {14,8,5,11, 13,7,4,16,10, 15,9,6,17,12, 3,1,0,2};
static const int ordD[17] = {14,8,5,11, 13,7,4,16,10, 15,9,6,17,12, 3,0,2};

static bool match_order(const int* ord, int n, const int* in_sizes, int n_in, int scale) {
  if (n != n_in) return false;
  for (int p = 0; p < n; p++) {
    long long L = kLogicalSz[ord[p]];
    long long s = in_sizes[p];
    if (L == 1) { if (s != 1 && s != 4 && s != 8) return false; }
    else if (s != L * scale) return false;
  }
  return true;
}

extern "C" void kernel_launch(void* const* d_in, const int* in_sizes, int n_in,
                              void* d_out, int out_size) {
  const void* slot[N_LOGICAL];
  for (int i = 0; i < N_LOGICAL; i++) slot[i] = nullptr;
  int gn_elems = 1;

  const int* ord = nullptr; int n = 0;
  for (int sc = 1; sc <= 4 && !ord; sc *= 4) {
    if      (match_order(ordA, 18, in_sizes, n_in, sc)) { ord = ordA; n = 18; }
    else if (match_order(ordB, 17, in_sizes, n_in, sc)) { ord = ordB; n = 17; }
    else if (match_order(ordC, 18, in_sizes, n_in, sc)) { ord = ordC; n = 18; }
    else if (match_order(ordD, 17, in_sizes, n_in, sc)) { ord = ordD; n = 17; }
  }
  if (ord) {
    for (int p = 0; p < n; p++) {
      slot[ord[p]] = d_in[p];
      if (ord[p] == 1) gn_elems = (in_sizes[p] >= 8) ? 2 : 1;
    }
  } else {
    long long scale = 1;
    for (int p = 0; p < n_in; p++) if (in_sizes[p] == 10240000) scale = 4;
    int wq[4] = {4,7,10,13}, uq[4] = {5,8,11,14}, bq[4] = {6,9,12,15};
    int wi_ = 0, ui_ = 0, bi_ = 0;
    for (int p = 0; p < n_in; p++) {
      long long s = in_sizes[p];
      if      (s == 2048*scale)    slot[0]  = d_in[p];
      else if (s == 1 || s == 4 || s == 8) { slot[1] = d_in[p]; gn_elems = (s >= 8) ? 2 : 1; }
      else if (s == 64*scale)      slot[2]  = d_in[p];
      else if (s == 2560000*scale) slot[3]  = d_in[p];
      else if (s == 5120000*scale) slot[16] = d_in[p];
      else if (s == 10000*scale)   slot[17] = d_in[p];
      else if (s == 131072*scale && wi_ < 4) slot[wq[wi_++]] = d_in[p];
      else if (s == 262144*scale && ui_ < 4) slot[uq[ui_++]] = d_in[p];
      else if (s == 512*scale    && bi_ < 4) slot[bq[bi_++]] = d_in[p];
    }
  }
  for (int i = 0; i < N_LOGICAL; i++)
    if (i != 1 && slot[i] == nullptr) return;

  const uint32_t* input_x     = (const uint32_t*)slot[0];
  const uint32_t* gn_dev      = (const uint32_t*)slot[1];
  const uint32_t* start_token = (const uint32_t*)slot[2];
  const float* emb = (const float*)slot[3];
  const float* Wi  = (const float*)slot[4];
  const float* Ui  = (const float*)slot[5];
  const float* bi  = (const float*)slot[6];
  const float* Wf  = (const float*)slot[7];
  const float* Uf  = (const float*)slot[8];
  const float* bf_ = (const float*)slot[9];
  const float* Wog = (const float*)slot[10];
  const float* Uog = (const float*)slot[11];
  const float* bog = (const float*)slot[12];
  const float* Wc  = (const float*)slot[13];
  const float* Uc  = (const float*)slot[14];
  const float* bc  = (const float*)slot[15];
  const float* Wo  = (const float*)slot[16];
  const float* bo  = (const float*)slot[17];

  init_kernel<<<Bsz, 256>>>(start_token, emb);
  for (int t = 0; t < Tsz; t++) {
    gates_kernel<<<dim3(8,4,8), 256>>>(Wi, Wf, Wog, Wc, Ui, Uf, Uog, Uc);
    cell_kernel<<<BH/256, 256>>>(bi, bf_, bog, bc);
    logits_partial_kernel<<<dim3(VT,LSPLIT), 256>>>(Wo);
    combine_kernel<<<VT, 256>>>(bo, t);
    finalize_kernel<<<Bsz, 256>>>(input_x, gn_dev, gn_elems, emb, (float*)d_out, t);
  }
}